// round 1
// baseline (speedup 1.0000x reference)
#include <cuda_runtime.h>
#include <math.h>

// Problem constants
#define NFFT     1024
#define HOP      256
#define SIGLEN   524288
#define NBATCH   32
#define GROUP    8            // output frames per CTA
#define NFRAMES  9            // FFT frames per CTA (GROUP+1)
#define NBINS    512          // output freq bins (k = 1..512)
#define THREADS  512
#define XBUFLEN  (GROUP*HOP + NFFT)   // 3072

__device__ __forceinline__ float wrap_pi(float d) {
    const float INV2PI = 0.15915494309189535f;
    const float TWOPI  = 6.283185307179586f;
    return d - TWOPI * rintf(d * INV2PI);
}

// radix-2 DIT stages on bit-reversed-loaded data in shared memory.
// 512 threads, one butterfly per thread per stage.
__device__ __forceinline__ void fft1024(float2* S, const float2* TW, int tid) {
    #pragma unroll
    for (int s = 0; s < 10; s++) {
        const int half = 1 << s;
        const int pos  = tid & (half - 1);
        const int i0   = ((tid >> s) << (s + 1)) | pos;
        const int i1   = i0 + half;
        const float2 w = TW[pos << (9 - s)];
        float2 a = S[i0];
        float2 b = S[i1];
        float tre = w.x * b.x - w.y * b.y;
        float tim = w.x * b.y + w.y * b.x;
        S[i0] = make_float2(a.x + tre, a.y + tim);
        S[i1] = make_float2(a.x - tre, a.y - tim);
        __syncthreads();
    }
}

extern __shared__ float smem_raw[];

__global__ __launch_bounds__(THREADS, 1)
void stft_kernel(const float* __restrict__ x, float* __restrict__ out)
{
    // ---- shared layout ----
    float2* S    = (float2*)smem_raw;            // 1024 * 8B  = 8192B
    float2* TW   = S + NFFT;                     // 512  * 8B  = 4096B
    float*  win  = (float*)(TW + 512);           // 1024 * 4B  = 4096B
    float*  xbuf = win + NFFT;                   // 3072 * 4B  = 12288B
    float*  ph   = xbuf + XBUFLEN;               // 9*512*4B   = 18432B
    float*  lm   = ph + NFRAMES * NBINS;         // 8*512*4B   = 16384B

    const int tid = threadIdx.x;
    const int grp = blockIdx.x;   // 0..255 (group of 8 output frames)
    const int b   = blockIdx.y;   // 0..31  (batch)

    // ---- twiddle table + hann window ----
    {
        // TW[p] = exp(-2*pi*i*p/1024), p in [0,512)
        float ang = -6.283185307179586f * (float)tid * (1.0f / 1024.0f);
        float sv, cv;
        sincosf(ang, &sv, &cv);
        TW[tid] = make_float2(cv, sv);
        #pragma unroll
        for (int n = tid; n < NFFT; n += THREADS)
            win[n] = 0.5f - 0.5f * cosf(6.283185307179586f * (float)n * (1.0f / 1024.0f));
    }

    // ---- load input window with reflect padding ----
    {
        const long base = (long)grp * (GROUP * HOP) - (NFFT / 2);
        const float* xb = x + (long)b * SIGLEN;
        #pragma unroll
        for (int i = tid; i < XBUFLEN; i += THREADS) {
            long p = base + i;
            if (p < 0) p = -p;
            else if (p >= SIGLEN) p = 2L * (SIGLEN - 1) - p;
            xbuf[i] = xb[p];
        }
    }
    __syncthreads();

    // ---- 5 complex FFTs covering 9 real frames (pairs packed in re/im) ----
    #pragma unroll
    for (int pr = 0; pr < 5; pr++) {
        const int gA = 2 * pr;
        const int gB = 2 * pr + 1;
        const bool hasB = (gB < NFRAMES);

        // windowed, bit-reverse-permuted load
        #pragma unroll
        for (int n = tid; n < NFFT; n += THREADS) {
            const float w  = win[n];
            const float re = w * xbuf[gA * HOP + n];
            const float im = hasB ? w * xbuf[gB * HOP + n] : 0.0f;
            const int   r  = __brev((unsigned)n) >> 22;
            S[r] = make_float2(re, im);
        }
        __syncthreads();

        fft1024(S, TW, tid);   // ends with __syncthreads

        // unpack spectra of the two packed real signals; k = tid+1 (skip DC)
        {
            const int k = tid + 1;
            const float2 Zk = S[k];
            const float2 Zr = S[NFFT - k];
            // A = spectrum of frame gA
            const float Are = 0.5f * (Zk.x + Zr.x);
            const float Aim = 0.5f * (Zk.y - Zr.y);
            ph[gA * NBINS + tid] = atan2f(Aim, Are);
            if (gA > 0) {
                const float m2 = Are * Are + Aim * Aim;
                lm[(gA - 1) * NBINS + tid] =
                    (0.5f * logf(fmaxf(m2, 1e-14f)) + 17.0f) * (1.0f / 23.0f);
            }
            if (hasB) {
                // B = spectrum of frame gB
                const float Bre = 0.5f * (Zk.y + Zr.y);
                const float Bim = 0.5f * (Zr.x - Zk.x);
                ph[gB * NBINS + tid] = atan2f(Bim, Bre);
                const float m2 = Bre * Bre + Bim * Bim;
                lm[(gB - 1) * NBINS + tid] =
                    (0.5f * logf(fmaxf(m2, 1e-14f)) + 17.0f) * (1.0f / 23.0f);
            }
        }
        __syncthreads();   // before S reuse
    }

    // ---- final coalesced writeout: thread tid owns freq row f=tid ----
    {
        const int f = tid;
        float m[GROUP], d[GROUP];
        #pragma unroll
        for (int j = 0; j < GROUP; j++) {
            m[j] = lm[j * NBINS + f];
            d[j] = wrap_pi(ph[(j + 1) * NBINS + f] - ph[j * NBINS + f]);
        }
        const long t0 = (long)grp * GROUP;
        float* o0 = out + ((((long)b * 2 + 0) * 512 + f) * 2048 + t0);
        float* o1 = out + ((((long)b * 2 + 1) * 512 + f) * 2048 + t0);
        ((float4*)o0)[0] = make_float4(m[0], m[1], m[2], m[3]);
        ((float4*)o0)[1] = make_float4(m[4], m[5], m[6], m[7]);
        ((float4*)o1)[0] = make_float4(d[0], d[1], d[2], d[3]);
        ((float4*)o1)[1] = make_float4(d[4], d[5], d[6], d[7]);
    }
}

extern "C" void kernel_launch(void* const* d_in, const int* in_sizes, int n_in,
                              void* d_out, int out_size)
{
    (void)in_sizes; (void)n_in; (void)out_size;
    const float* x = (const float*)d_in[0];
    float* out = (float*)d_out;

    const size_t shmem =
        NFFT * sizeof(float2) +          // S
        512  * sizeof(float2) +          // TW
        NFFT * sizeof(float)  +          // win
        XBUFLEN * sizeof(float) +        // xbuf
        NFRAMES * NBINS * sizeof(float) +// ph
        GROUP   * NBINS * sizeof(float); // lm

    cudaFuncSetAttribute(stft_kernel,
                         cudaFuncAttributeMaxDynamicSharedMemorySize,
                         (int)shmem);

    dim3 grid(2048 / GROUP, NBATCH);   // (256, 32)
    stft_kernel<<<grid, THREADS, shmem>>>(x, out);
}